// round 16
// baseline (speedup 1.0000x reference)
#include <cuda_runtime.h>
#include <cuda_bf16.h>
#include <math.h>
#include <cstdint>

#define B_ 2
#define S_ 2048
#define D_ 1024
#define H_ 16
#define HD_ 64
#define EPS_ 1e-5f
// 1/sqrt(1024) * log2(e)
#define QSCALE_ 0.04508422f
#define BHS_ (B_ * H_ * S_)

// ---------------- scratch ----------------
__device__ __nv_bfloat16 g_hb[B_ * S_ * D_];
__device__ __nv_bfloat16 g_qb[B_ * S_ * D_];
__device__ __nv_bfloat16 g_kb[B_ * S_ * D_];
__device__ __nv_bfloat16 g_vb[B_ * S_ * D_];
__device__ __nv_bfloat16 g_cb[B_ * S_ * D_];
__device__ float         g_esump[BHS_ * 4];      // [idx][split]
__device__ float         g_ediag[BHS_];
__device__ float         g_tsum[B_ * H_ * 128 * HD_];   // 16-row tiles
__device__ __nv_bfloat16 g_wqkv[3 * D_ * D_];    // packed [3072,1024]
__device__ float         g_bqkv[3 * D_];         // packed bias
__device__ __nv_bfloat16 g_wob[D_ * D_];

// ---------------- helpers ----------------
__device__ __forceinline__ uint32_t smem_u32(const void* p) {
    uint32_t a;
    asm("{ .reg .u64 t; cvta.to.shared.u64 t, %1; cvt.u32.u64 %0, t; }" : "=r"(a) : "l"(p));
    return a;
}
__device__ __forceinline__ void cp_async16(uint32_t dst, const void* src) {
    asm volatile("cp.async.cg.shared.global [%0], [%1], 16;" :: "r"(dst), "l"(src));
}
#define CP_COMMIT() asm volatile("cp.async.commit_group;" ::: "memory")

__device__ __forceinline__ void mma_bf16(float c[4], const uint32_t a[4], const uint32_t b[2]) {
    asm volatile(
        "mma.sync.aligned.m16n8k16.row.col.f32.bf16.bf16.f32 "
        "{%0,%1,%2,%3}, {%4,%5,%6,%7}, {%8,%9}, {%0,%1,%2,%3};"
        : "+f"(c[0]), "+f"(c[1]), "+f"(c[2]), "+f"(c[3])
        : "r"(a[0]), "r"(a[1]), "r"(a[2]), "r"(a[3]), "r"(b[0]), "r"(b[1]));
}
__device__ __forceinline__ void ldsm4(uint32_t* r, uint32_t addr) {
    asm volatile("ldmatrix.sync.aligned.m8n8.x4.shared.b16 {%0,%1,%2,%3}, [%4];"
        : "=r"(r[0]), "=r"(r[1]), "=r"(r[2]), "=r"(r[3]) : "r"(addr));
}
__device__ __forceinline__ float ex2f(float x) {
    float y;
    asm("ex2.approx.f32 %0, %1;" : "=f"(y) : "f"(x));
    return y;
}

// ================= bf16 mma GEMM (128x128 tile, 4 warps x 64x64, BK=64, 3 stages) =================
#define BG_STAGEB 16384
#define BG_SMEMB  (3 * BG_STAGEB * 2)   // 96 KB

__device__ __forceinline__ void bg_load_stage(uint32_t sbase, const __nv_bfloat16* A,
                                              const __nv_bfloat16* W,
                                              int bm, int bn, int it, int slot, int tid) {
    const int k0 = it * 64;
    const uint32_t abase = sbase + slot * BG_STAGEB;
    const uint32_t bbase = sbase + (3 + slot) * BG_STAGEB;
    #pragma unroll
    for (int i = 0; i < 8; i++) {
        const int c = tid + i * 128;  // 0..1023
        const int row = c >> 3;
        const int c4 = c & 7;
        const uint32_t off = (uint32_t)(row * 128 + ((c4 ^ (row & 7)) << 4));
        cp_async16(abase + off, A + (size_t)(bm + row) * D_ + k0 + c4 * 8);
        cp_async16(bbase + off, W + (size_t)(bn + row) * D_ + k0 + c4 * 8);
    }
    CP_COMMIT();
}

__global__ __launch_bounds__(128, 2) void gemm_bf16(const __nv_bfloat16* __restrict__ A,
                                                    const __nv_bfloat16* __restrict__ W,
                                                    const float* __restrict__ biasP,
                                                    __nv_bfloat16* __restrict__ Cq,
                                                    __nv_bfloat16* __restrict__ Ck,
                                                    __nv_bfloat16* __restrict__ Cv,
                                                    float* __restrict__ Cf,
                                                    const float* __restrict__ res) {
    extern __shared__ char smc[];
    const uint32_t sbase = smem_u32(smc);
    const int tid = threadIdx.x;
    const int wid = tid >> 5, lane = tid & 31;
    const int g = lane >> 2, tg = lane & 3;
    const int wm = (wid & 1) * 64, wn = (wid >> 1) * 64;
    const int bm = blockIdx.y * 128, bn = blockIdx.x * 128;

    // ldmatrix per-lane offsets
    const int lr = lane & 7;
    const int row_in = ((lane >> 3) & 1) * 8 + lr;
    const int gh = (lane >> 4) & 1;
    const int lm = (lane >> 3) & 3;
    uint32_t aoff[4], boff[2];
    #pragma unroll
    for (int ks = 0; ks < 4; ks++)
        aoff[ks] = (uint32_t)(row_in * 128 + (((2 * ks + gh) ^ lr) << 4));
    boff[0] = (uint32_t)(lr * 128 + ((lm ^ lr) << 4));
    boff[1] = (uint32_t)(lr * 128 + (((lm + 4) ^ lr) << 4));

    float acc[4][8][4];
    #pragma unroll
    for (int i = 0; i < 4; i++)
        #pragma unroll
        for (int j = 0; j < 8; j++)
            #pragma unroll
            for (int e = 0; e < 4; e++) acc[i][j][e] = 0.f;

    bg_load_stage(sbase, A, W, bm, bn, 0, 0, tid);
    bg_load_stage(sbase, A, W, bm, bn, 1, 1, tid);

    const int nIter = D_ / 64;  // 16
    for (int it = 0; it < nIter; it++) {
        const int slot = it % 3;
        if (it < nIter - 1) {
            asm volatile("cp.async.wait_group 1;" ::: "memory");
        } else {
            asm volatile("cp.async.wait_group 0;" ::: "memory");
        }
        __syncthreads();
        if (it + 2 < nIter) bg_load_stage(sbase, A, W, bm, bn, it + 2, (it + 2) % 3, tid);

        const uint32_t aST = sbase + slot * BG_STAGEB;
        const uint32_t bST = sbase + (3 + slot) * BG_STAGEB;

        #pragma unroll
        for (int p = 0; p < 2; p++) {
            uint32_t a0[4][4], a1[4][4], b0[8][2], b1[8][2];
            #pragma unroll
            for (int j = 0; j < 8; j++) {
                uint32_t t[4];
                ldsm4(t, bST + (uint32_t)((wn + j * 8) * 128) + boff[p]);
                b0[j][0] = t[0]; b0[j][1] = t[1];
                b1[j][0] = t[2]; b1[j][1] = t[3];
            }
            #pragma unroll
            for (int i = 0; i < 4; i++) {
                ldsm4(a0[i], aST + (uint32_t)((wm + i * 16) * 128) + aoff[2 * p]);
                ldsm4(a1[i], aST + (uint32_t)((wm + i * 16) * 128) + aoff[2 * p + 1]);
            }
            #pragma unroll
            for (int i = 0; i < 4; i++)
                #pragma unroll
                for (int j = 0; j < 8; j++) mma_bf16(acc[i][j], a0[i], b0[j]);
            #pragma unroll
            for (int i = 0; i < 4; i++)
                #pragma unroll
                for (int j = 0; j < 8; j++) mma_bf16(acc[i][j], a1[i], b1[j]);
        }
    }

    // epilogue
    __nv_bfloat16* Cb = nullptr;
    float oscale = 1.f;
    if (Cq) {
        const int mi = bn >> 10;
        Cb = (mi == 0) ? Cq : (mi == 1) ? Ck : Cv;
        if (mi == 0) oscale = QSCALE_;   // fold score scale*log2e into Q
    }
    #pragma unroll
    for (int i = 0; i < 4; i++) {
        const int row = bm + wm + i * 16 + g;
        #pragma unroll
        for (int j = 0; j < 8; j++) {
            const int gn = bn + wn + j * 8 + tg * 2;
            const int col = gn & 1023;
            const float2 bv = *(const float2*)(biasP + gn);
            float o00 = (acc[i][j][0] + bv.x) * oscale, o01 = (acc[i][j][1] + bv.y) * oscale;
            float o10 = (acc[i][j][2] + bv.x) * oscale, o11 = (acc[i][j][3] + bv.y) * oscale;
            if (res) {
                const float2 r0 = *(const float2*)(res + (size_t)row * D_ + col);
                const float2 r1 = *(const float2*)(res + (size_t)(row + 8) * D_ + col);
                o00 += r0.x; o01 += r0.y;
                o10 += r1.x; o11 += r1.y;
            }
            if (Cb) {
                __nv_bfloat162 h0, h1;
                h0.x = __float2bfloat16(o00); h0.y = __float2bfloat16(o01);
                h1.x = __float2bfloat16(o10); h1.y = __float2bfloat16(o11);
                *(__nv_bfloat162*)(Cb + (size_t)row * D_ + col) = h0;
                *(__nv_bfloat162*)(Cb + (size_t)(row + 8) * D_ + col) = h1;
            } else {
                *(float2*)(Cf + (size_t)row * D_ + col) = make_float2(o00, o01);
                *(float2*)(Cf + (size_t)(row + 8) * D_ + col) = make_float2(o10, o11);
            }
        }
    }
}

// ---------------- fused prep: LayerNorm + weight/bias conversion ----------------
__global__ void prep_kernel(const float* __restrict__ x,
                            const float* __restrict__ gamma,
                            const float* __restrict__ beta,
                            const float* __restrict__ wq, const float* __restrict__ wk,
                            const float* __restrict__ wv, const float* __restrict__ wo,
                            const float* __restrict__ bq, const float* __restrict__ bk,
                            const float* __restrict__ bv,
                            __nv_bfloat16* __restrict__ hb,
                            __nv_bfloat16* __restrict__ wqkv,
                            __nv_bfloat16* __restrict__ wob,
                            float* __restrict__ bqkv) {
    const int bid = blockIdx.x;
    const int tid = threadIdx.x;

    if (bid < 4096) {
        // ---- LayerNorm row ----
        const int row = bid;
        const float* xr = x + (size_t)row * D_;
        float4 xv = ((const float4*)xr)[tid];
        float sum = xv.x + xv.y + xv.z + xv.w;
        float sq  = xv.x * xv.x + xv.y * xv.y + xv.z * xv.z + xv.w * xv.w;

        __shared__ float2 red[32];
        float2 v2 = make_float2(sum, sq);
        #pragma unroll
        for (int o = 16; o > 0; o >>= 1) {
            v2.x += __shfl_down_sync(0xffffffffu, v2.x, o);
            v2.y += __shfl_down_sync(0xffffffffu, v2.y, o);
        }
        if ((tid & 31) == 0) red[tid >> 5] = v2;
        __syncthreads();
        if (tid < 32) {
            float2 w = (tid < 8) ? red[tid] : make_float2(0.f, 0.f);
            #pragma unroll
            for (int o = 4; o > 0; o >>= 1) {
                w.x += __shfl_down_sync(0xffffffffu, w.x, o);
                w.y += __shfl_down_sync(0xffffffffu, w.y, o);
            }
            if (tid == 0) red[0] = w;
        }
        __syncthreads();
        const float mu  = red[0].x * (1.0f / D_);
        const float var = red[0].y * (1.0f / D_) - mu * mu;
        const float inv = rsqrtf(var + EPS_);

        float4 gm = ((const float4*)gamma)[tid];
        float4 b = ((const float4*)beta)[tid];
        __nv_bfloat162 p0, p1;
        p0.x = __float2bfloat16((xv.x - mu) * inv * gm.x + b.x);
        p0.y = __float2bfloat16((xv.y - mu) * inv * gm.y + b.y);
        p1.x = __float2bfloat16((xv.z - mu) * inv * gm.z + b.z);
        p1.y = __float2bfloat16((xv.w - mu) * inv * gm.w + b.w);
        __nv_bfloat162* op = (__nv_bfloat162*)(hb + (size_t)row * D_);
        op[2 * tid] = p0;
        op[2 * tid + 1] = p1;
    } else if (bid < 5120) {
        // ---- weight convert (MLP=4) ----
        const int cb = bid - 4096;
        const int m = cb >> 8;
        const int j = ((cb & 255) << 8) + tid;  // 0..65535
        const float* in = (m == 0) ? wq : (m == 1) ? wk : (m == 2) ? wv : wo;
        __nv_bfloat16* out = (m == 3) ? wob : (wqkv + (size_t)m * D_ * D_);
        float4 v[4];
        #pragma unroll
        for (int u = 0; u < 4; u++) v[u] = ((const float4*)in)[j + u * 65536];
        #pragma unroll
        for (int u = 0; u < 4; u++) {
            __nv_bfloat162 a, b;
            a.x = __float2bfloat16(v[u].x); a.y = __float2bfloat16(v[u].y);
            b.x = __float2bfloat16(v[u].z); b.y = __float2bfloat16(v[u].w);
            ((__nv_bfloat162*)out)[2 * (j + u * 65536)] = a;
            ((__nv_bfloat162*)out)[2 * (j + u * 65536) + 1] = b;
        }
    } else {
        // ---- bias pack ----
        for (int i = tid; i < D_; i += 256) {
            bqkv[i] = bq[i];
            bqkv[D_ + i] = bk[i];
            bqkv[2 * D_ + i] = bv[i];
        }
    }
}

// ---------------- scores via bf16 mma + ldmatrix, split-K z=4 (+16-row tilesum at z=4) ----------------
#define SC_SMEMB (3 * 16384)

__device__ __forceinline__ void sc_load_tile(uint32_t dst, const __nv_bfloat16* src,
                                             int rowbase, int hh, int tid) {
    #pragma unroll
    for (int i = 0; i < 4; i++) {
        const int c = tid + i * 256;
        const int row = c >> 3;
        const int c4 = c & 7;
        const uint32_t off = (uint32_t)(row * 128 + ((c4 ^ (row & 7)) << 4));
        cp_async16(dst + off, src + (size_t)(rowbase + row) * D_ + hh * HD_ + c4 * 8);
    }
}

__global__ __launch_bounds__(256) void scores_mma(const __nv_bfloat16* __restrict__ Qb,
                                                  const __nv_bfloat16* __restrict__ Kb,
                                                  const __nv_bfloat16* __restrict__ Vb,
                                                  float* __restrict__ esump,
                                                  float* __restrict__ ediag,
                                                  float* __restrict__ tsum) {
    extern __shared__ char sms[];
    const uint32_t sbase = smem_u32(sms);
    const uint32_t* su = (const uint32_t*)sms;
    const int tid = threadIdx.x;
    const int qt = blockIdx.x;
    const int bh = blockIdx.y;
    const int s  = blockIdx.z;
    const int b = bh >> 4, hh = bh & 15;

    if (s == 4) {
        // ---- tilesum: 8 x 16-row tiles per block (2 items/thread) ----
        #pragma unroll
        for (int itx = 0; itx < 2; itx++) {
            const int idx = tid + itx * 256;
            const int tloc = idx >> 6;          // 0..7
            const int d = idx & 63;
            const int t = qt * 8 + tloc;        // 0..127
            const size_t base = ((size_t)b * S_) * D_ + hh * HD_ + d;
            const int s0 = t * 16;
            float sm = 0.f;
            #pragma unroll
            for (int c8 = 0; c8 < 2; c8++) {
                __nv_bfloat16 tv[8];
                #pragma unroll
                for (int u = 0; u < 8; u++)
                    tv[u] = Vb[base + (size_t)(s0 + c8 * 8 + u) * D_];
                #pragma unroll
                for (int u = 0; u < 8; u++) sm += __bfloat162float(tv[u]);
            }
            tsum[(bh * 128 + t) * 64 + d] = sm;
        }
        return;
    }

    const int wid = tid >> 5, lane = tid & 31;
    const int g = lane >> 2, tg = lane & 3;
    const int q0 = qt * 128;
    const int r0 = q0 + wid * 16 + g;
    const int r1 = r0 + 8;

    const int n = 16 - qt;
    const int qsz = (n + 3) >> 2;
    const int kts = qt + s * qsz;
    const int kte = min(16, kts + qsz);

    if (kts >= kte) {
        if (tg == 0) {
            esump[(bh * S_ + r0) * 4 + s] = 0.f;
            esump[(bh * S_ + r1) * 4 + s] = 0.f;
        }
        return;
    }

    sc_load_tile(sbase, Qb, b * S_ + q0, hh, tid);
    sc_load_tile(sbase + 16384, Kb, b * S_ + kts * 128, hh, tid);
    CP_COMMIT();
    asm volatile("cp.async.wait_group 0;" ::: "memory");
    __syncthreads();

    const int lr = lane & 7;
    const int lm = (lane >> 3) & 3;
    const uint32_t boff0 = (uint32_t)(lr * 128 + ((lm ^ lr) << 4));
    const uint32_t boff1 = (uint32_t)(lr * 128 + (((lm + 4) ^ lr) << 4));

    int pidx[4][2];
    #pragma unroll
    for (int ks = 0; ks < 4; ks++) {
        pidx[ks][0] = (ks * 8 + tg) ^ (g << 2);
        pidx[ks][1] = (ks * 8 + 4 + tg) ^ (g << 2);
    }
    uint32_t af[4][4];
    {
        const int rowa = wid * 16 + g;
        #pragma unroll
        for (int ks = 0; ks < 4; ks++) {
            af[ks][0] = su[rowa * 32 + pidx[ks][0]];
            af[ks][1] = su[(rowa + 8) * 32 + pidx[ks][0]];
            af[ks][2] = su[rowa * 32 + pidx[ks][1]];
            af[ks][3] = su[(rowa + 8) * 32 + pidx[ks][1]];
        }
    }

    float racc0 = 0.f, racc1 = 0.f, ed0 = 0.f, ed1 = 0.f;

    for (int kt = kts; kt < kte; kt++) {
        const int buf = (kt - kts) & 1;
        if (kt + 1 < kte) {
            sc_load_tile(sbase + 16384 + (buf ^ 1) * 16384, Kb, b * S_ + (kt + 1) * 128, hh, tid);
            CP_COMMIT();
        }
        const uint32_t ktile = sbase + 16384 + buf * 16384;

        if (kt == qt) {
            const int kbase = kt * 128;
            #pragma unroll 4
            for (int j = 0; j < 16; j++) {
                uint32_t t0[4], t1[4];
                const uint32_t kaddr = ktile + (uint32_t)(j * 8) * 128;
                ldsm4(t0, kaddr + boff0);
                ldsm4(t1, kaddr + boff1);
                float c[4] = {0.f, 0.f, 0.f, 0.f};
                mma_bf16(c, af[0], &t0[0]);
                mma_bf16(c, af[1], &t0[2]);
                mma_bf16(c, af[2], &t1[0]);
                mma_bf16(c, af[3], &t1[2]);
                const int col0 = kbase + j * 8 + tg * 2;
                const int col1 = col0 + 1;
                float e00 = (col0 >= r0) ? ex2f(c[0]) : 0.f;
                float e01 = (col1 >= r0) ? ex2f(c[1]) : 0.f;
                float e10 = (col0 >= r1) ? ex2f(c[2]) : 0.f;
                float e11 = (col1 >= r1) ? ex2f(c[3]) : 0.f;
                racc0 += e00 + e01;
                racc1 += e10 + e11;
                if (col0 == r0) ed0 = e00;
                if (col1 == r0) ed0 = e01;
                if (col0 == r1) ed1 = e10;
                if (col1 == r1) ed1 = e11;
            }
        } else {
            #pragma unroll 4
            for (int j = 0; j < 16; j++) {
                uint32_t t0[4], t1[4];
                const uint32_t kaddr = ktile + (uint32_t)(j * 8) * 128;
                ldsm4(t0, kaddr + boff0);
                ldsm4(t1, kaddr + boff1);
                float c[4] = {0.f, 0.f, 0.f, 0.f};
                mma_bf16(c, af[0], &t0[0]);
                mma_bf16(c, af[1], &t0[2]);
                mma_bf16(c, af[2], &t1[0]);
                mma_bf16(c, af[3], &t1[2]);
                racc0 += ex2f(c[0]) + ex2f(c[1]);
                racc1 += ex2f(c[2]) + ex2f(c[3]);
            }
        }
        if (kt + 1 < kte) asm volatile("cp.async.wait_group 0;" ::: "memory");
        __syncthreads();
    }

    #pragma unroll
    for (int o = 1; o <= 2; o <<= 1) {
        racc0 += __shfl_xor_sync(0xffffffffu, racc0, o);
        racc1 += __shfl_xor_sync(0xffffffffu, racc1, o);
        ed0   += __shfl_xor_sync(0xffffffffu, ed0, o);
        ed1   += __shfl_xor_sync(0xffffffffu, ed1, o);
    }
    if (tg == 0) {
        esump[(bh * S_ + r0) * 4 + s] = racc0;
        esump[(bh * S_ + r1) * 4 + s] = racc1;
        if (s == 0) {
            ediag[bh * S_ + r0] = ed0;
            ediag[bh * S_ + r1] = ed1;
        }
    }
}

// ---------------- attention output: 16-row tiles, 1 warp/tile, batched loads ----------------
__global__ __launch_bounds__(128) void attnout_kernel(const __nv_bfloat16* __restrict__ V,
                                                      const float* __restrict__ tsum,
                                                      const float* __restrict__ esump,
                                                      const float* __restrict__ ediag,
                                                      __nv_bfloat16* __restrict__ out) {
    const int tg4 = blockIdx.x;          // 0..31
    const int bh  = blockIdx.y;
    const int wid = threadIdx.x >> 5;    // 0..3
    const int lane = threadIdx.x & 31;
    const int t = tg4 * 4 + wid;         // 0..127 (16-row tiles)
    const int b  = bh / H_;
    const int hh = bh % H_;
    const int s0 = t * 16;

    __shared__ float s_e[4][16];
    __shared__ float s_inv[4][16];

    if (lane < 16) {
        const int q = s0 + lane;
        const float4 p = *(const float4*)(esump + (size_t)(bh * S_ + q) * 4);
        s_inv[wid][lane] = __frcp_rn((float)q + p.x + p.y + p.z + p.w);
        s_e[wid][lane]   = ediag[bh * S_ + q];
    }

    const size_t base = ((size_t)b * S_) * D_ + hh * HD_ + 2 * lane;

    // batch-load all 16 V values first (independent; overlaps prefix latency)
    uint32_t vr[16];
    #pragma unroll
    for (int i = 0; i < 16; i++)
        vr[i] = *(const uint32_t*)(V + base + (size_t)(s0 + i) * D_);

    // chunked prefix over 16-row tile sums
    float2 run = make_float2(0.f, 0.f);
    const float* tbase = tsum + bh * 128 * 64 + 2 * lane;
    int tt = 0;
    for (; tt + 8 <= t; tt += 8) {
        float2 tmp[8];
        #pragma unroll
        for (int u = 0; u < 8; u++)
            tmp[u] = *(const float2*)(tbase + (tt + u) * 64);
        #pragma unroll
        for (int u = 0; u < 8; u++) { run.x += tmp[u].x; run.y += tmp[u].y; }
    }
    for (; tt < t; tt++) {
        const float2 v = *(const float2*)(tbase + tt * 64);
        run.x += v.x; run.y += v.y;
    }

    __syncwarp();

    #pragma unroll
    for (int i = 0; i < 16; i++) {
        const __nv_bfloat162 vv = *(const __nv_bfloat162*)&vr[i];
        const float v0 = __bfloat162float(vv.x);
        const float v1 = __bfloat162float(vv.y);
        const float e   = s_e[wid][i];
        const float inv = s_inv[wid][i];
        __nv_bfloat162 o;
        o.x = __float2bfloat16((run.x + e * v0) * inv);
        o.y = __float2bfloat16((run.y + e * v1) * inv);
        *(__nv_bfloat162*)(out + base + (size_t)(s0 + i) * D_) = o;
        run.x += v0; run.y += v1;
    }
}

// ---------------- launch ----------------
extern "C" void kernel_launch(void* const* d_in, const int* in_sizes, int n_in,
                              void* d_out, int out_size) {
    const float* x     = (const float*)d_in[0];
    const float* wq    = (const float*)d_in[1];
    const float* bq    = (const float*)d_in[2];
    const float* wk    = (const float*)d_in[3];
    const float* bk    = (const float*)d_in[4];
    const float* wv    = (const float*)d_in[5];
    const float* bv    = (const float*)d_in[6];
    const float* wo    = (const float*)d_in[7];
    const float* bo    = (const float*)d_in[8];
    const float* gamma = (const float*)d_in[9];
    const float* beta  = (const float*)d_in[10];
    float* out = (float*)d_out;

    __nv_bfloat16 *hb, *qb, *kb, *vb, *cb, *wqkv, *wob;
    float *esump, *ediag, *tsum, *bqkv;
    cudaGetSymbolAddress((void**)&hb,    g_hb);
    cudaGetSymbolAddress((void**)&qb,    g_qb);
    cudaGetSymbolAddress((void**)&kb,    g_kb);
    cudaGetSymbolAddress((void**)&vb,    g_vb);
    cudaGetSymbolAddress((void**)&cb,    g_cb);
    cudaGetSymbolAddress((void**)&esump, g_esump);
    cudaGetSymbolAddress((void**)&ediag, g_ediag);
    cudaGetSymbolAddress((void**)&tsum,  g_tsum);
    cudaGetSymbolAddress((void**)&wqkv,  g_wqkv);
    cudaGetSymbolAddress((void**)&wob,   g_wob);
    cudaGetSymbolAddress((void**)&bqkv,  g_bqkv);

    cudaFuncSetAttribute(gemm_bf16, cudaFuncAttributeMaxDynamicSharedMemorySize, BG_SMEMB);
    cudaFuncSetAttribute(scores_mma, cudaFuncAttributeMaxDynamicSharedMemorySize, SC_SMEMB);

    const int M = B_ * S_;  // 4096

    // fused LN + weight/bias conversion
    prep_kernel<<<5121, 256>>>(x, gamma, beta, wq, wk, wv, wo, bq, bk, bv,
                               hb, wqkv, wob, bqkv);

    // fused QKV: N=3072 (Q slice pre-scaled by 1/sqrt(D)*log2e)
    dim3 gq(3 * D_ / 128, M / 128);  // (24, 32)
    gemm_bf16<<<gq, 128, BG_SMEMB>>>(hb, wqkv, bqkv, qb, kb, vb, nullptr, nullptr);

    // scores (z=0..3) + tilesum (z=4)
    dim3 gs(16, B_ * H_, 5);
    scores_mma<<<gs, 256, SC_SMEMB>>>(qb, kb, vb, esump, ediag, tsum);

    // attention output: 16-row tiles, 1024 blocks
    dim3 ga(32, B_ * H_);
    attnout_kernel<<<ga, 128>>>(vb, tsum, esump, ediag, cb);

    // output projection: N=1024, fp32 out with residual
    dim3 go(D_ / 128, M / 128);  // (8, 32)
    gemm_bf16<<<go, 128, BG_SMEMB>>>(cb, wob, bo, nullptr, nullptr, nullptr, out, x);
}

// round 17
// speedup vs baseline: 1.0267x; 1.0267x over previous
#include <cuda_runtime.h>
#include <cuda_bf16.h>
#include <math.h>
#include <cstdint>

#define B_ 2
#define S_ 2048
#define D_ 1024
#define H_ 16
#define HD_ 64
#define EPS_ 1e-5f
// 1/sqrt(1024) * log2(e)
#define QSCALE_ 0.04508422f
#define BHS_ (B_ * H_ * S_)

// ---------------- scratch ----------------
__device__ __nv_bfloat16 g_hb[B_ * S_ * D_];
__device__ __nv_bfloat16 g_qb[B_ * S_ * D_];
__device__ __nv_bfloat16 g_kb[B_ * S_ * D_];
__device__ __nv_bfloat16 g_vb[B_ * S_ * D_];
__device__ __nv_bfloat16 g_cb[B_ * S_ * D_];
__device__ float         g_esump[BHS_ * 4];     // [idx][split]
__device__ float         g_ediag[BHS_];
__device__ float         g_tsum[B_ * H_ * 64 * HD_];
__device__ __nv_bfloat16 g_wqkv[3 * D_ * D_];   // packed [3072,1024]
__device__ float         g_bqkv[3 * D_];        // packed bias
__device__ __nv_bfloat16 g_wob[D_ * D_];

// ---------------- helpers ----------------
__device__ __forceinline__ uint32_t smem_u32(const void* p) {
    uint32_t a;
    asm("{ .reg .u64 t; cvta.to.shared.u64 t, %1; cvt.u32.u64 %0, t; }" : "=r"(a) : "l"(p));
    return a;
}
__device__ __forceinline__ void cp_async16(uint32_t dst, const void* src) {
    asm volatile("cp.async.cg.shared.global [%0], [%1], 16;" :: "r"(dst), "l"(src));
}
#define CP_COMMIT() asm volatile("cp.async.commit_group;" ::: "memory")

__device__ __forceinline__ void mma_bf16(float c[4], const uint32_t a[4], const uint32_t b[2]) {
    asm volatile(
        "mma.sync.aligned.m16n8k16.row.col.f32.bf16.bf16.f32 "
        "{%0,%1,%2,%3}, {%4,%5,%6,%7}, {%8,%9}, {%0,%1,%2,%3};"
        : "+f"(c[0]), "+f"(c[1]), "+f"(c[2]), "+f"(c[3])
        : "r"(a[0]), "r"(a[1]), "r"(a[2]), "r"(a[3]), "r"(b[0]), "r"(b[1]));
}
__device__ __forceinline__ void ldsm4(uint32_t* r, uint32_t addr) {
    asm volatile("ldmatrix.sync.aligned.m8n8.x4.shared.b16 {%0,%1,%2,%3}, [%4];"
        : "=r"(r[0]), "=r"(r[1]), "=r"(r[2]), "=r"(r[3]) : "r"(addr));
}
__device__ __forceinline__ float ex2f(float x) {
    float y;
    asm("ex2.approx.f32 %0, %1;" : "=f"(y) : "f"(x));
    return y;
}

// ================= bf16 mma GEMM (128x128 tile, 4 warps x 64x64, BK=64, 3 stages) =================
#define BG_STAGEB 16384
#define BG_SMEMB  (3 * BG_STAGEB * 2)   // 96 KB

__device__ __forceinline__ void bg_load_stage(uint32_t sbase, const __nv_bfloat16* A,
                                              const __nv_bfloat16* W,
                                              int bm, int bn, int it, int slot, int tid) {
    const int k0 = it * 64;
    const uint32_t abase = sbase + slot * BG_STAGEB;
    const uint32_t bbase = sbase + (3 + slot) * BG_STAGEB;
    #pragma unroll
    for (int i = 0; i < 8; i++) {
        const int c = tid + i * 128;  // 0..1023
        const int row = c >> 3;
        const int c4 = c & 7;
        const uint32_t off = (uint32_t)(row * 128 + ((c4 ^ (row & 7)) << 4));
        cp_async16(abase + off, A + (size_t)(bm + row) * D_ + k0 + c4 * 8);
        cp_async16(bbase + off, W + (size_t)(bn + row) * D_ + k0 + c4 * 8);
    }
    CP_COMMIT();
}

__global__ __launch_bounds__(128, 2) void gemm_bf16(const __nv_bfloat16* __restrict__ A,
                                                    const __nv_bfloat16* __restrict__ W,
                                                    const float* __restrict__ biasP,
                                                    __nv_bfloat16* __restrict__ Cq,
                                                    __nv_bfloat16* __restrict__ Ck,
                                                    __nv_bfloat16* __restrict__ Cv,
                                                    float* __restrict__ Cf,
                                                    const float* __restrict__ res) {
    extern __shared__ char smc[];
    const uint32_t sbase = smem_u32(smc);
    const int tid = threadIdx.x;
    const int wid = tid >> 5, lane = tid & 31;
    const int g = lane >> 2, tg = lane & 3;
    const int wm = (wid & 1) * 64, wn = (wid >> 1) * 64;
    const int bm = blockIdx.y * 128, bn = blockIdx.x * 128;

    // ldmatrix per-lane offsets
    const int lr = lane & 7;
    const int row_in = ((lane >> 3) & 1) * 8 + lr;
    const int gh = (lane >> 4) & 1;
    const int lm = (lane >> 3) & 3;
    uint32_t aoff[4], boff[2];
    #pragma unroll
    for (int ks = 0; ks < 4; ks++)
        aoff[ks] = (uint32_t)(row_in * 128 + (((2 * ks + gh) ^ lr) << 4));
    boff[0] = (uint32_t)(lr * 128 + ((lm ^ lr) << 4));
    boff[1] = (uint32_t)(lr * 128 + (((lm + 4) ^ lr) << 4));

    float acc[4][8][4];
    #pragma unroll
    for (int i = 0; i < 4; i++)
        #pragma unroll
        for (int j = 0; j < 8; j++)
            #pragma unroll
            for (int e = 0; e < 4; e++) acc[i][j][e] = 0.f;

    bg_load_stage(sbase, A, W, bm, bn, 0, 0, tid);
    bg_load_stage(sbase, A, W, bm, bn, 1, 1, tid);

    const int nIter = D_ / 64;  // 16
    for (int it = 0; it < nIter; it++) {
        const int slot = it % 3;
        if (it < nIter - 1) {
            asm volatile("cp.async.wait_group 1;" ::: "memory");
        } else {
            asm volatile("cp.async.wait_group 0;" ::: "memory");
        }
        __syncthreads();
        if (it + 2 < nIter) bg_load_stage(sbase, A, W, bm, bn, it + 2, (it + 2) % 3, tid);

        const uint32_t aST = sbase + slot * BG_STAGEB;
        const uint32_t bST = sbase + (3 + slot) * BG_STAGEB;

        #pragma unroll
        for (int p = 0; p < 2; p++) {
            uint32_t a0[4][4], a1[4][4], b0[8][2], b1[8][2];
            #pragma unroll
            for (int j = 0; j < 8; j++) {
                uint32_t t[4];
                ldsm4(t, bST + (uint32_t)((wn + j * 8) * 128) + boff[p]);
                b0[j][0] = t[0]; b0[j][1] = t[1];
                b1[j][0] = t[2]; b1[j][1] = t[3];
            }
            #pragma unroll
            for (int i = 0; i < 4; i++) {
                ldsm4(a0[i], aST + (uint32_t)((wm + i * 16) * 128) + aoff[2 * p]);
                ldsm4(a1[i], aST + (uint32_t)((wm + i * 16) * 128) + aoff[2 * p + 1]);
            }
            #pragma unroll
            for (int i = 0; i < 4; i++)
                #pragma unroll
                for (int j = 0; j < 8; j++) mma_bf16(acc[i][j], a0[i], b0[j]);
            #pragma unroll
            for (int i = 0; i < 4; i++)
                #pragma unroll
                for (int j = 0; j < 8; j++) mma_bf16(acc[i][j], a1[i], b1[j]);
        }
    }

    // epilogue
    __nv_bfloat16* Cb = nullptr;
    float oscale = 1.f;
    if (Cq) {
        const int mi = bn >> 10;
        Cb = (mi == 0) ? Cq : (mi == 1) ? Ck : Cv;
        if (mi == 0) oscale = QSCALE_;   // fold score scale*log2e into Q
    }
    #pragma unroll
    for (int i = 0; i < 4; i++) {
        const int row = bm + wm + i * 16 + g;
        #pragma unroll
        for (int j = 0; j < 8; j++) {
            const int gn = bn + wn + j * 8 + tg * 2;
            const int col = gn & 1023;
            const float2 bv = *(const float2*)(biasP + gn);
            float o00 = (acc[i][j][0] + bv.x) * oscale, o01 = (acc[i][j][1] + bv.y) * oscale;
            float o10 = (acc[i][j][2] + bv.x) * oscale, o11 = (acc[i][j][3] + bv.y) * oscale;
            if (res) {
                const float2 r0 = *(const float2*)(res + (size_t)row * D_ + col);
                const float2 r1 = *(const float2*)(res + (size_t)(row + 8) * D_ + col);
                o00 += r0.x; o01 += r0.y;
                o10 += r1.x; o11 += r1.y;
            }
            if (Cb) {
                __nv_bfloat162 h0, h1;
                h0.x = __float2bfloat16(o00); h0.y = __float2bfloat16(o01);
                h1.x = __float2bfloat16(o10); h1.y = __float2bfloat16(o11);
                *(__nv_bfloat162*)(Cb + (size_t)row * D_ + col) = h0;
                *(__nv_bfloat162*)(Cb + (size_t)(row + 8) * D_ + col) = h1;
            } else {
                *(float2*)(Cf + (size_t)row * D_ + col) = make_float2(o00, o01);
                *(float2*)(Cf + (size_t)(row + 8) * D_ + col) = make_float2(o10, o11);
            }
        }
    }
}

// ---------------- fused prep: LayerNorm + weight/bias conversion ----------------
__global__ void prep_kernel(const float* __restrict__ x,
                            const float* __restrict__ gamma,
                            const float* __restrict__ beta,
                            const float* __restrict__ wq, const float* __restrict__ wk,
                            const float* __restrict__ wv, const float* __restrict__ wo,
                            const float* __restrict__ bq, const float* __restrict__ bk,
                            const float* __restrict__ bv,
                            __nv_bfloat16* __restrict__ hb,
                            __nv_bfloat16* __restrict__ wqkv,
                            __nv_bfloat16* __restrict__ wob,
                            float* __restrict__ bqkv) {
    const int bid = blockIdx.x;
    const int tid = threadIdx.x;

    if (bid < 4096) {
        // ---- LayerNorm row ----
        const int row = bid;
        const float* xr = x + (size_t)row * D_;
        float4 xv = ((const float4*)xr)[tid];
        float sum = xv.x + xv.y + xv.z + xv.w;
        float sq  = xv.x * xv.x + xv.y * xv.y + xv.z * xv.z + xv.w * xv.w;

        __shared__ float2 red[32];
        float2 v2 = make_float2(sum, sq);
        #pragma unroll
        for (int o = 16; o > 0; o >>= 1) {
            v2.x += __shfl_down_sync(0xffffffffu, v2.x, o);
            v2.y += __shfl_down_sync(0xffffffffu, v2.y, o);
        }
        if ((tid & 31) == 0) red[tid >> 5] = v2;
        __syncthreads();
        if (tid < 32) {
            float2 w = (tid < 8) ? red[tid] : make_float2(0.f, 0.f);
            #pragma unroll
            for (int o = 4; o > 0; o >>= 1) {
                w.x += __shfl_down_sync(0xffffffffu, w.x, o);
                w.y += __shfl_down_sync(0xffffffffu, w.y, o);
            }
            if (tid == 0) red[0] = w;
        }
        __syncthreads();
        const float mu  = red[0].x * (1.0f / D_);
        const float var = red[0].y * (1.0f / D_) - mu * mu;
        const float inv = rsqrtf(var + EPS_);

        float4 gm = ((const float4*)gamma)[tid];
        float4 b = ((const float4*)beta)[tid];
        __nv_bfloat162 p0, p1;
        p0.x = __float2bfloat16((xv.x - mu) * inv * gm.x + b.x);
        p0.y = __float2bfloat16((xv.y - mu) * inv * gm.y + b.y);
        p1.x = __float2bfloat16((xv.z - mu) * inv * gm.z + b.z);
        p1.y = __float2bfloat16((xv.w - mu) * inv * gm.w + b.w);
        __nv_bfloat162* op = (__nv_bfloat162*)(hb + (size_t)row * D_);
        op[2 * tid] = p0;
        op[2 * tid + 1] = p1;
    } else if (bid < 5120) {
        // ---- weight convert (MLP=4) ----
        const int cb = bid - 4096;
        const int m = cb >> 8;
        const int j = ((cb & 255) << 8) + tid;  // 0..65535
        const float* in = (m == 0) ? wq : (m == 1) ? wk : (m == 2) ? wv : wo;
        __nv_bfloat16* out = (m == 3) ? wob : (wqkv + (size_t)m * D_ * D_);
        float4 v[4];
        #pragma unroll
        for (int u = 0; u < 4; u++) v[u] = ((const float4*)in)[j + u * 65536];
        #pragma unroll
        for (int u = 0; u < 4; u++) {
            __nv_bfloat162 a, b;
            a.x = __float2bfloat16(v[u].x); a.y = __float2bfloat16(v[u].y);
            b.x = __float2bfloat16(v[u].z); b.y = __float2bfloat16(v[u].w);
            ((__nv_bfloat162*)out)[2 * (j + u * 65536)] = a;
            ((__nv_bfloat162*)out)[2 * (j + u * 65536) + 1] = b;
        }
    } else {
        // ---- bias pack ----
        for (int i = tid; i < D_; i += 256) {
            bqkv[i] = bq[i];
            bqkv[D_ + i] = bk[i];
            bqkv[2 * D_ + i] = bv[i];
        }
    }
}

// ---------------- scores via bf16 mma + ldmatrix, split-K z=4 (+tilesum at z=4) ----------------
#define SC_SMEMB (3 * 16384)

__device__ __forceinline__ void sc_load_tile(uint32_t dst, const __nv_bfloat16* src,
                                             int rowbase, int hh, int tid) {
    #pragma unroll
    for (int i = 0; i < 4; i++) {
        const int c = tid + i * 256;
        const int row = c >> 3;
        const int c4 = c & 7;
        const uint32_t off = (uint32_t)(row * 128 + ((c4 ^ (row & 7)) << 4));
        cp_async16(dst + off, src + (size_t)(rowbase + row) * D_ + hh * HD_ + c4 * 8);
    }
}

__global__ __launch_bounds__(256) void scores_mma(const __nv_bfloat16* __restrict__ Qb,
                                                  const __nv_bfloat16* __restrict__ Kb,
                                                  const __nv_bfloat16* __restrict__ Vb,
                                                  float* __restrict__ esump,
                                                  float* __restrict__ ediag,
                                                  float* __restrict__ tsum) {
    extern __shared__ char sms[];
    const uint32_t sbase = smem_u32(sms);
    const uint32_t* su = (const uint32_t*)sms;
    const int tid = threadIdx.x;
    const int qt = blockIdx.x;
    const int bh = blockIdx.y;
    const int s  = blockIdx.z;
    const int b = bh >> 4, hh = bh & 15;

    if (s == 4) {
        // ---- tilesum: 4 x 32-row tiles per block ----
        const int t = qt * 4 + (tid >> 6);   // 0..63
        const int d = tid & 63;
        const size_t base = ((size_t)b * S_) * D_ + hh * HD_ + d;
        const int s0 = t * 32;
        float sm = 0.f;
        #pragma unroll 8
        for (int i = 0; i < 32; i++) sm += __bfloat162float(Vb[base + (size_t)(s0 + i) * D_]);
        tsum[(bh * 64 + t) * 64 + d] = sm;
        return;
    }

    const int wid = tid >> 5, lane = tid & 31;
    const int g = lane >> 2, tg = lane & 3;
    const int q0 = qt * 128;
    const int r0 = q0 + wid * 16 + g;
    const int r1 = r0 + 8;

    const int n = 16 - qt;
    const int qsz = (n + 3) >> 2;
    const int kts = qt + s * qsz;
    const int kte = min(16, kts + qsz);

    if (kts >= kte) {
        if (tg == 0) {
            esump[(bh * S_ + r0) * 4 + s] = 0.f;
            esump[(bh * S_ + r1) * 4 + s] = 0.f;
        }
        return;
    }

    sc_load_tile(sbase, Qb, b * S_ + q0, hh, tid);
    sc_load_tile(sbase + 16384, Kb, b * S_ + kts * 128, hh, tid);
    CP_COMMIT();
    asm volatile("cp.async.wait_group 0;" ::: "memory");
    __syncthreads();

    const int lr = lane & 7;
    const int lm = (lane >> 3) & 3;
    const uint32_t boff0 = (uint32_t)(lr * 128 + ((lm ^ lr) << 4));
    const uint32_t boff1 = (uint32_t)(lr * 128 + (((lm + 4) ^ lr) << 4));

    int pidx[4][2];
    #pragma unroll
    for (int ks = 0; ks < 4; ks++) {
        pidx[ks][0] = (ks * 8 + tg) ^ (g << 2);
        pidx[ks][1] = (ks * 8 + 4 + tg) ^ (g << 2);
    }
    uint32_t af[4][4];
    {
        const int rowa = wid * 16 + g;
        #pragma unroll
        for (int ks = 0; ks < 4; ks++) {
            af[ks][0] = su[rowa * 32 + pidx[ks][0]];
            af[ks][1] = su[(rowa + 8) * 32 + pidx[ks][0]];
            af[ks][2] = su[rowa * 32 + pidx[ks][1]];
            af[ks][3] = su[(rowa + 8) * 32 + pidx[ks][1]];
        }
    }

    float racc0 = 0.f, racc1 = 0.f, ed0 = 0.f, ed1 = 0.f;

    for (int kt = kts; kt < kte; kt++) {
        const int buf = (kt - kts) & 1;
        if (kt + 1 < kte) {
            sc_load_tile(sbase + 16384 + (buf ^ 1) * 16384, Kb, b * S_ + (kt + 1) * 128, hh, tid);
            CP_COMMIT();
        }
        const uint32_t ktile = sbase + 16384 + buf * 16384;

        if (kt == qt) {
            const int kbase = kt * 128;
            #pragma unroll 4
            for (int j = 0; j < 16; j++) {
                uint32_t t0[4], t1[4];
                const uint32_t kaddr = ktile + (uint32_t)(j * 8) * 128;
                ldsm4(t0, kaddr + boff0);
                ldsm4(t1, kaddr + boff1);
                float c[4] = {0.f, 0.f, 0.f, 0.f};
                mma_bf16(c, af[0], &t0[0]);
                mma_bf16(c, af[1], &t0[2]);
                mma_bf16(c, af[2], &t1[0]);
                mma_bf16(c, af[3], &t1[2]);
                const int col0 = kbase + j * 8 + tg * 2;
                const int col1 = col0 + 1;
                float e00 = (col0 >= r0) ? ex2f(c[0]) : 0.f;
                float e01 = (col1 >= r0) ? ex2f(c[1]) : 0.f;
                float e10 = (col0 >= r1) ? ex2f(c[2]) : 0.f;
                float e11 = (col1 >= r1) ? ex2f(c[3]) : 0.f;
                racc0 += e00 + e01;
                racc1 += e10 + e11;
                if (col0 == r0) ed0 = e00;
                if (col1 == r0) ed0 = e01;
                if (col0 == r1) ed1 = e10;
                if (col1 == r1) ed1 = e11;
            }
        } else {
            #pragma unroll 4
            for (int j = 0; j < 16; j++) {
                uint32_t t0[4], t1[4];
                const uint32_t kaddr = ktile + (uint32_t)(j * 8) * 128;
                ldsm4(t0, kaddr + boff0);
                ldsm4(t1, kaddr + boff1);
                float c[4] = {0.f, 0.f, 0.f, 0.f};
                mma_bf16(c, af[0], &t0[0]);
                mma_bf16(c, af[1], &t0[2]);
                mma_bf16(c, af[2], &t1[0]);
                mma_bf16(c, af[3], &t1[2]);
                racc0 += ex2f(c[0]) + ex2f(c[1]);
                racc1 += ex2f(c[2]) + ex2f(c[3]);
            }
        }
        if (kt + 1 < kte) asm volatile("cp.async.wait_group 0;" ::: "memory");
        __syncthreads();
    }

    #pragma unroll
    for (int o = 1; o <= 2; o <<= 1) {
        racc0 += __shfl_xor_sync(0xffffffffu, racc0, o);
        racc1 += __shfl_xor_sync(0xffffffffu, racc1, o);
        ed0   += __shfl_xor_sync(0xffffffffu, ed0, o);
        ed1   += __shfl_xor_sync(0xffffffffu, ed1, o);
    }
    if (tg == 0) {
        esump[(bh * S_ + r0) * 4 + s] = racc0;
        esump[(bh * S_ + r1) * 4 + s] = racc1;
        if (s == 0) {
            ediag[bh * S_ + r0] = ed0;
            ediag[bh * S_ + r1] = ed1;
        }
    }
}

// ---------------- exclusive prefix scan over tile sums (in place) ----------------
// grid: 32 (bh); block: 64 threads (d). Each thread owns one column of 64 tiles.
__global__ __launch_bounds__(64) void scan_kernel(float* __restrict__ tsum) {
    const int bh = blockIdx.x;
    const int d = threadIdx.x;
    float* col = tsum + bh * 64 * 64 + d;

    float v[64];
    #pragma unroll
    for (int t = 0; t < 64; t++) v[t] = col[t * 64];   // independent loads

    float run = 0.f;
    #pragma unroll
    for (int t = 0; t < 64; t++) {                      // exclusive scan, t ascending
        const float cur = v[t];
        v[t] = run;
        run += cur;
    }

    #pragma unroll
    for (int t = 0; t < 64; t++) col[t * 64] = v[t];
}

// ---------------- attention output: precomputed prefix, batched V loads ----------------
__global__ __launch_bounds__(128) void attnout_kernel(const __nv_bfloat16* __restrict__ V,
                                                      const float* __restrict__ tsum,
                                                      const float* __restrict__ esump,
                                                      const float* __restrict__ ediag,
                                                      __nv_bfloat16* __restrict__ out) {
    const int tg4 = blockIdx.x;          // 0..15
    const int bh  = blockIdx.y;
    const int wid = threadIdx.x >> 5;    // 0..3
    const int lane = threadIdx.x & 31;
    const int t = tg4 * 4 + wid;         // 0..63
    const int b  = bh / H_;
    const int hh = bh % H_;
    const int s0 = t * 32;

    __shared__ float s_e[4][32];
    __shared__ float s_inv[4][32];

    {
        const int q = s0 + lane;
        const float4 p = *(const float4*)(esump + (size_t)(bh * S_ + q) * 4);
        s_inv[wid][lane] = __frcp_rn((float)q + p.x + p.y + p.z + p.w);
        s_e[wid][lane]   = ediag[bh * S_ + q];
    }

    const size_t base = ((size_t)b * S_) * D_ + hh * HD_ + 2 * lane;

    // exclusive prefix of V over preceding tiles: one load (precomputed by scan_kernel)
    float2 run = *(const float2*)(tsum + (bh * 64 + t) * 64 + 2 * lane);

    // batch-load all 32 V values (one latency exposure)
    uint32_t vr[32];
    #pragma unroll
    for (int i = 0; i < 32; i++)
        vr[i] = *(const uint32_t*)(V + base + (size_t)(s0 + i) * D_);

    __syncwarp();

    #pragma unroll
    for (int i = 0; i < 32; i++) {
        const __nv_bfloat162 vv = *(const __nv_bfloat162*)&vr[i];
        const float v0 = __bfloat162float(vv.x);
        const float v1 = __bfloat162float(vv.y);
        const float e   = s_e[wid][i];
        const float inv = s_inv[wid][i];
        __nv_bfloat162 o;
        o.x = __float2bfloat16((run.x + e * v0) * inv);
        o.y = __float2bfloat16((run.y + e * v1) * inv);
        *(__nv_bfloat162*)(out + base + (size_t)(s0 + i) * D_) = o;
        run.x += v0; run.y += v1;
    }
}

// ---------------- launch ----------------
extern "C" void kernel_launch(void* const* d_in, const int* in_sizes, int n_in,
                              void* d_out, int out_size) {
    const float* x     = (const float*)d_in[0];
    const float* wq    = (const float*)d_in[1];
    const float* bq    = (const float*)d_in[2];
    const float* wk    = (const float*)d_in[3];
    const float* bk    = (const float*)d_in[4];
    const float* wv    = (const float*)d_in[5];
    const float* bv    = (const float*)d_in[6];
    const float* wo    = (const float*)d_in[7];
    const float* bo    = (const float*)d_in[8];
    const float* gamma = (const float*)d_in[9];
    const float* beta  = (const float*)d_in[10];
    float* out = (float*)d_out;

    __nv_bfloat16 *hb, *qb, *kb, *vb, *cb, *wqkv, *wob;
    float *esump, *ediag, *tsum, *bqkv;
    cudaGetSymbolAddress((void**)&hb,    g_hb);
    cudaGetSymbolAddress((void**)&qb,    g_qb);
    cudaGetSymbolAddress((void**)&kb,    g_kb);
    cudaGetSymbolAddress((void**)&vb,    g_vb);
    cudaGetSymbolAddress((void**)&cb,    g_cb);
    cudaGetSymbolAddress((void**)&esump, g_esump);
    cudaGetSymbolAddress((void**)&ediag, g_ediag);
    cudaGetSymbolAddress((void**)&tsum,  g_tsum);
    cudaGetSymbolAddress((void**)&wqkv,  g_wqkv);
    cudaGetSymbolAddress((void**)&wob,   g_wob);
    cudaGetSymbolAddress((void**)&bqkv,  g_bqkv);

    cudaFuncSetAttribute(gemm_bf16, cudaFuncAttributeMaxDynamicSharedMemorySize, BG_SMEMB);
    cudaFuncSetAttribute(scores_mma, cudaFuncAttributeMaxDynamicSharedMemorySize, SC_SMEMB);

    const int M = B_ * S_;  // 4096

    // fused LN + weight/bias conversion
    prep_kernel<<<5121, 256>>>(x, gamma, beta, wq, wk, wv, wo, bq, bk, bv,
                               hb, wqkv, wob, bqkv);

    // fused QKV: N=3072 (Q slice pre-scaled by 1/sqrt(D)*log2e)
    dim3 gq(3 * D_ / 128, M / 128);  // (24, 32)
    gemm_bf16<<<gq, 128, BG_SMEMB>>>(hb, wqkv, bqkv, qb, kb, vb, nullptr, nullptr);

    // scores (z=0..3) + tilesum (z=4)
    dim3 gs(16, B_ * H_, 5);
    scores_mma<<<gs, 256, SC_SMEMB>>>(qb, kb, vb, esump, ediag, tsum);

    // exclusive scan of tile sums
    scan_kernel<<<B_ * H_, 64>>>(tsum);

    // attention output
    dim3 ga(16, B_ * H_);
    attnout_kernel<<<ga, 128>>>(vb, tsum, esump, ediag, cb);

    // output projection: N=1024, fp32 out with residual
    dim3 go(D_ / 128, M / 128);  // (8, 32)
    gemm_bf16<<<go, 128, BG_SMEMB>>>(cb, wob, bo, nullptr, nullptr, nullptr, out, x);
}